// round 3
// baseline (speedup 1.0000x reference)
#include <cuda_runtime.h>
#include <math.h>

// Problem constants
#define NROWS   16384
#define HD      256
#define H3      768
#define TSTEPS  24

// Tiling
#define MTILE   128                  // rows per CTA
#define NBLK    (NROWS / MTILE)      // 128 CTAs
#define UCHUNK  32                   // hidden units per chunk (computes r,z,n triple)
#define NCHUNKS (HD / UCHUNK)        // 8
#define KTILE   32
#define NKT     (HD / KTILE)         // 8
#define HPAD    257                  // smem h row pitch (conflict-free)
#define WPAD    33                   // smem W row pitch (conflict-free)
#define WROWS   (3 * UCHUNK)         // 96 W rows per chunk (r,z,n blocks)

// Persistent device state (no allocations allowed)
__device__ float g_h[NROWS * HD];    // hidden state [N,H]
__device__ float g_x[NROWS];         // current scalar input per row
__device__ float g_A[H3];            // W_ih @ w_proj
__device__ float g_C[H3];            // W_ih @ b_proj + b_ih

// smem floats: h tile + W tile + A + C + b_hh + w_out + x
#define SMEM_FLOATS (MTILE * HPAD + WROWS * WPAD + 3 * H3 + HD + MTILE)
#define SMEM_BYTES  (SMEM_FLOATS * 4)

// ---------------------------------------------------------------------------
// init: h0 = encoder_out, x0 = 0, A = W_ih@w_proj, C = W_ih@b_proj + b_ih
// ---------------------------------------------------------------------------
__global__ void init_kernel(const float* __restrict__ enc,
                            const float* __restrict__ w_proj,
                            const float* __restrict__ b_proj,
                            const float* __restrict__ W_ih,
                            const float* __restrict__ b_ih)
{
    int tid = blockIdx.x * blockDim.x + threadIdx.x;
    int nth = gridDim.x * blockDim.x;
    for (int i = tid; i < NROWS * HD; i += nth) g_h[i] = enc[i];
    for (int i = tid; i < NROWS; i += nth)      g_x[i] = 0.0f;

    int warp = tid >> 5, lane = tid & 31, nwarps = nth >> 5;
    for (int j = warp; j < H3; j += nwarps) {
        float sa = 0.0f, sb = 0.0f;
        for (int k = lane; k < HD; k += 32) {
            float w = W_ih[j * HD + k];
            sa += w * w_proj[k];
            sb += w * b_proj[k];
        }
        #pragma unroll
        for (int o = 16; o > 0; o >>= 1) {
            sa += __shfl_xor_sync(0xffffffffu, sa, o);
            sb += __shfl_xor_sync(0xffffffffu, sb, o);
        }
        if (lane == 0) { g_A[j] = sa; g_C[j] = sb + b_ih[j]; }
    }
}

// ---------------------------------------------------------------------------
// One fused GRU step:
//   gh = h @ W_hh^T (+ b_hh), gates, h_new, pred = h_new@w_out + b_out
//   out[:, t] = pred; x = pred; h = h_new
// Block: 256 threads as (tx 0..15, ty 0..15); each thread: 8 rows x 6 cols
// (cols = 2 hidden units x {r,z,n}).
// ---------------------------------------------------------------------------
extern "C" __global__ void __launch_bounds__(256, 1)
step_kernel(const float* __restrict__ W_hh,   // [768,256]
            const float* __restrict__ b_hh,   // [768]
            const float* __restrict__ w_out,  // [256]
            const float* __restrict__ b_out,  // [1]
            float* __restrict__ out,          // [N,24]
            int t)
{
    extern __shared__ float smem[];
    float* sh_h = smem;                        // [128][257]
    float* sw   = sh_h + MTILE * HPAD;         // [96][33]
    float* sA   = sw + WROWS * WPAD;           // [768]
    float* sC   = sA + H3;                     // [768]
    float* sbh  = sC + H3;                     // [768]
    float* swo  = sbh + H3;                    // [256]
    float* sx   = swo + HD;                    // [128]

    const int tid = threadIdx.x;
    const int tx  = tid & 15;
    const int ty  = tid >> 4;
    const int row0 = blockIdx.x * MTILE;

    // Stage h tile (coalesced float4 global reads, padded scalar smem stores)
    {
        const float4* gh4 = (const float4*)(g_h + row0 * HD);
        for (int idx = tid; idx < MTILE * (HD / 4); idx += 256) {
            int r  = idx >> 6;        // /64 float4 per row
            int c4 = idx & 63;
            float4 v = gh4[r * 64 + c4];
            float* d = sh_h + r * HPAD + c4 * 4;
            d[0] = v.x; d[1] = v.y; d[2] = v.z; d[3] = v.w;
        }
    }
    for (int i = tid; i < H3; i += 256) { sA[i] = g_A[i]; sC[i] = g_C[i]; sbh[i] = b_hh[i]; }
    for (int i = tid; i < HD; i += 256) swo[i] = w_out[i];
    if (tid < MTILE) sx[tid] = g_x[row0 + tid];
    __syncthreads();

    float pr[8];                        // pred partial per owned row
    #pragma unroll
    for (int i = 0; i < 8; i++) pr[i] = 0.0f;

    const int j0 = tx * 2;              // local unit pair within chunk

    for (int chunk = 0; chunk < NCHUNKS; chunk++) {
        const int u0 = chunk * UCHUNK;

        float acc[8][6];
        #pragma unroll
        for (int i = 0; i < 8; i++)
            #pragma unroll
            for (int j = 0; j < 6; j++) acc[i][j] = 0.0f;

        for (int kt = 0; kt < NKT; kt++) {
            const int k0 = kt * KTILE;
            __syncthreads();            // protect sw reuse
            // Load W tile: rows {u0..u0+31} of r, z, n blocks; cols k0..k0+31
            #pragma unroll
            for (int p = 0; p < 3; p++) {
                int li  = p * 256 + tid;       // 0..767 float4 slots
                int rr  = li >> 3;             // 0..95 tile row
                int c4  = li & 7;              // float4 within row
                int grow = (rr >> 5) * HD + u0 + (rr & 31); // global W_hh row
                float4 v = *(const float4*)(W_hh + grow * HD + k0 + c4 * 4);
                float* d = sw + rr * WPAD + c4 * 4;
                d[0] = v.x; d[1] = v.y; d[2] = v.z; d[3] = v.w;
            }
            __syncthreads();

            #pragma unroll 4
            for (int k = 0; k < KTILE; k++) {
                float hv[8];
                #pragma unroll
                for (int i = 0; i < 8; i++)
                    hv[i] = sh_h[(ty * 8 + i) * HPAD + k0 + k];
                float wr0 = sw[(j0     ) * WPAD + k];
                float wr1 = sw[(j0 +  1) * WPAD + k];
                float wz0 = sw[(j0 + 32) * WPAD + k];
                float wz1 = sw[(j0 + 33) * WPAD + k];
                float wn0 = sw[(j0 + 64) * WPAD + k];
                float wn1 = sw[(j0 + 65) * WPAD + k];
                #pragma unroll
                for (int i = 0; i < 8; i++) {
                    acc[i][0] = fmaf(hv[i], wr0, acc[i][0]);
                    acc[i][1] = fmaf(hv[i], wr1, acc[i][1]);
                    acc[i][2] = fmaf(hv[i], wz0, acc[i][2]);
                    acc[i][3] = fmaf(hv[i], wz1, acc[i][3]);
                    acc[i][4] = fmaf(hv[i], wn0, acc[i][4]);
                    acc[i][5] = fmaf(hv[i], wn1, acc[i][5]);
                }
            }
        }

        // Gate phase for this unit pair
        const int u = u0 + j0;
        float Ar0 = sA[u],        Ar1 = sA[u + 1];
        float Az0 = sA[256 + u],  Az1 = sA[257 + u];
        float An0 = sA[512 + u],  An1 = sA[513 + u];
        float Cr0 = sC[u]       + sbh[u],        Cr1 = sC[u + 1]   + sbh[u + 1];
        float Cz0 = sC[256 + u] + sbh[256 + u],  Cz1 = sC[257 + u] + sbh[257 + u];
        float Bn0 = sC[512 + u],  Bn1 = sC[513 + u];
        float bn0 = sbh[512 + u], bn1 = sbh[513 + u];
        float wo0 = swo[u],       wo1 = swo[u + 1];

        #pragma unroll
        for (int ri = 0; ri < 8; ri++) {
            const int rl = ty * 8 + ri;
            const float x = sx[rl];

            float gr0 = fmaf(x, Ar0, Cr0) + acc[ri][0];
            float gz0 = fmaf(x, Az0, Cz0) + acc[ri][2];
            float r0  = 1.0f / (1.0f + expf(-gr0));
            float z0  = 1.0f / (1.0f + expf(-gz0));
            float n0  = tanhf(fmaf(r0, acc[ri][4] + bn0, fmaf(x, An0, Bn0)));
            float ho0 = sh_h[rl * HPAD + u];
            float hn0 = fmaf(z0, ho0 - n0, n0);

            float gr1 = fmaf(x, Ar1, Cr1) + acc[ri][1];
            float gz1 = fmaf(x, Az1, Cz1) + acc[ri][3];
            float r1  = 1.0f / (1.0f + expf(-gr1));
            float z1  = 1.0f / (1.0f + expf(-gz1));
            float n1  = tanhf(fmaf(r1, acc[ri][5] + bn1, fmaf(x, An1, Bn1)));
            float ho1 = sh_h[rl * HPAD + u + 1];
            float hn1 = fmaf(z1, ho1 - n1, n1);

            float2 st; st.x = hn0; st.y = hn1;
            *(float2*)(g_h + (size_t)(row0 + rl) * HD + u) = st;

            // pred partial; reduce over the 16 tx lanes in this half-warp
            float p = hn0 * wo0 + hn1 * wo1;
            #pragma unroll
            for (int o = 8; o > 0; o >>= 1)
                p += __shfl_xor_sync(0xffffffffu, p, o);
            pr[ri] += p;      // valid on all lanes; only tx==0 consumes
        }
    }

    // Epilogue: one lane per half-warp owns rows ty*8..ty*8+7
    if (tx == 0) {
        float bo = b_out[0];
        #pragma unroll
        for (int ri = 0; ri < 8; ri++) {
            int row = row0 + ty * 8 + ri;
            float pred = pr[ri] + bo;
            out[(size_t)row * TSTEPS + t] = pred;
            g_x[row] = pred;
        }
    }
}

// ---------------------------------------------------------------------------
extern "C" void kernel_launch(void* const* d_in, const int* in_sizes, int n_in,
                              void* d_out, int out_size)
{
    const float* enc    = (const float*)d_in[0];
    const float* w_proj = (const float*)d_in[1];
    const float* b_proj = (const float*)d_in[2];
    const float* W_ih   = (const float*)d_in[3];
    const float* b_ih   = (const float*)d_in[4];
    const float* W_hh   = (const float*)d_in[5];
    const float* b_hh   = (const float*)d_in[6];
    const float* w_out  = (const float*)d_in[7];
    const float* b_out  = (const float*)d_in[8];
    float* out = (float*)d_out;

    cudaFuncSetAttribute(step_kernel,
                         cudaFuncAttributeMaxDynamicSharedMemorySize, SMEM_BYTES);

    init_kernel<<<256, 256>>>(enc, w_proj, b_proj, W_ih, b_ih);
    for (int t = 0; t < TSTEPS; t++)
        step_kernel<<<NBLK, 256, SMEM_BYTES>>>(W_hh, b_hh, w_out, b_out, out, t);
}

// round 5
// speedup vs baseline: 1.0007x; 1.0007x over previous
#include <cuda_runtime.h>
#include <math.h>

// Problem constants
#define NROWS   16384
#define HD      256
#define H3      768
#define TSTEPS  24

// Tiling
#define MTILE   128                  // rows per CTA
#define NBLK    (NROWS / MTILE)      // 128 CTAs
#define UCHUNK  32                   // hidden units per chunk (computes r,z,n triple)
#define NCHUNKS (HD / UCHUNK)        // 8
#define KTILE   32
#define NKT     (HD / KTILE)         // 8
#define HPAD    257                  // smem h row pitch (conflict-free)
#define WPAD    33                   // smem W row pitch (conflict-free)
#define WROWS   (3 * UCHUNK)         // 96 W rows per chunk (r,z,n blocks)

// Persistent device state (no allocations allowed)
__device__ float g_h[NROWS * HD];    // hidden state [N,H]
__device__ float g_x[NROWS];         // current scalar input per row
__device__ float g_A[H3];            // W_ih @ w_proj
__device__ float g_C[H3];            // W_ih @ b_proj + b_ih

// smem floats: h tile + W tile + A + C + b_hh + w_out + x
#define SMEM_FLOATS (MTILE * HPAD + WROWS * WPAD + 3 * H3 + HD + MTILE)
#define SMEM_BYTES  (SMEM_FLOATS * 4)

// ---------------------------------------------------------------------------
// init: h0 = encoder_out, x0 = 0, A = W_ih@w_proj, C = W_ih@b_proj + b_ih
// ---------------------------------------------------------------------------
__global__ void init_kernel(const float* __restrict__ enc,
                            const float* __restrict__ w_proj,
                            const float* __restrict__ b_proj,
                            const float* __restrict__ W_ih,
                            const float* __restrict__ b_ih)
{
    int tid = blockIdx.x * blockDim.x + threadIdx.x;
    int nth = gridDim.x * blockDim.x;
    for (int i = tid; i < NROWS * HD; i += nth) g_h[i] = enc[i];
    for (int i = tid; i < NROWS; i += nth)      g_x[i] = 0.0f;

    int warp = tid >> 5, lane = tid & 31, nwarps = nth >> 5;
    for (int j = warp; j < H3; j += nwarps) {
        float sa = 0.0f, sb = 0.0f;
        for (int k = lane; k < HD; k += 32) {
            float w = W_ih[j * HD + k];
            sa += w * w_proj[k];
            sb += w * b_proj[k];
        }
        #pragma unroll
        for (int o = 16; o > 0; o >>= 1) {
            sa += __shfl_xor_sync(0xffffffffu, sa, o);
            sb += __shfl_xor_sync(0xffffffffu, sb, o);
        }
        if (lane == 0) { g_A[j] = sa; g_C[j] = sb + b_ih[j]; }
    }
}

// ---------------------------------------------------------------------------
// One fused GRU step:
//   gh = h @ W_hh^T (+ b_hh), gates, h_new, pred = h_new@w_out + b_out
//   out[:, t] = pred; x = pred; h = h_new
// Block: 256 threads as (tx 0..15, ty 0..15); each thread: 8 rows x 6 cols
// (cols = 2 hidden units x {r,z,n}).
// ---------------------------------------------------------------------------
extern "C" __global__ void __launch_bounds__(256, 1)
step_kernel(const float* __restrict__ W_hh,   // [768,256]
            const float* __restrict__ b_hh,   // [768]
            const float* __restrict__ w_out,  // [256]
            const float* __restrict__ b_out,  // [1]
            float* __restrict__ out,          // [N,24]
            int t)
{
    extern __shared__ float smem[];
    float* sh_h = smem;                        // [128][257]
    float* sw   = sh_h + MTILE * HPAD;         // [96][33]
    float* sA   = sw + WROWS * WPAD;           // [768]
    float* sC   = sA + H3;                     // [768]
    float* sbh  = sC + H3;                     // [768]
    float* swo  = sbh + H3;                    // [256]
    float* sx   = swo + HD;                    // [128]

    const int tid = threadIdx.x;
    const int tx  = tid & 15;
    const int ty  = tid >> 4;
    const int row0 = blockIdx.x * MTILE;

    // Stage h tile (coalesced float4 global reads, padded scalar smem stores)
    {
        const float4* gh4 = (const float4*)(g_h + row0 * HD);
        for (int idx = tid; idx < MTILE * (HD / 4); idx += 256) {
            int r  = idx >> 6;        // /64 float4 per row
            int c4 = idx & 63;
            float4 v = gh4[r * 64 + c4];
            float* d = sh_h + r * HPAD + c4 * 4;
            d[0] = v.x; d[1] = v.y; d[2] = v.z; d[3] = v.w;
        }
    }
    for (int i = tid; i < H3; i += 256) { sA[i] = g_A[i]; sC[i] = g_C[i]; sbh[i] = b_hh[i]; }
    for (int i = tid; i < HD; i += 256) swo[i] = w_out[i];
    if (tid < MTILE) sx[tid] = g_x[row0 + tid];
    __syncthreads();

    float pr[8];                        // pred partial per owned row
    #pragma unroll
    for (int i = 0; i < 8; i++) pr[i] = 0.0f;

    const int j0 = tx * 2;              // local unit pair within chunk

    for (int chunk = 0; chunk < NCHUNKS; chunk++) {
        const int u0 = chunk * UCHUNK;

        float acc[8][6];
        #pragma unroll
        for (int i = 0; i < 8; i++)
            #pragma unroll
            for (int j = 0; j < 6; j++) acc[i][j] = 0.0f;

        for (int kt = 0; kt < NKT; kt++) {
            const int k0 = kt * KTILE;
            __syncthreads();            // protect sw reuse
            // Load W tile: rows {u0..u0+31} of r, z, n blocks; cols k0..k0+31
            #pragma unroll
            for (int p = 0; p < 3; p++) {
                int li  = p * 256 + tid;       // 0..767 float4 slots
                int rr  = li >> 3;             // 0..95 tile row
                int c4  = li & 7;              // float4 within row
                int grow = (rr >> 5) * HD + u0 + (rr & 31); // global W_hh row
                float4 v = *(const float4*)(W_hh + grow * HD + k0 + c4 * 4);
                float* d = sw + rr * WPAD + c4 * 4;
                d[0] = v.x; d[1] = v.y; d[2] = v.z; d[3] = v.w;
            }
            __syncthreads();

            #pragma unroll 4
            for (int k = 0; k < KTILE; k++) {
                float hv[8];
                #pragma unroll
                for (int i = 0; i < 8; i++)
                    hv[i] = sh_h[(ty * 8 + i) * HPAD + k0 + k];
                float wr0 = sw[(j0     ) * WPAD + k];
                float wr1 = sw[(j0 +  1) * WPAD + k];
                float wz0 = sw[(j0 + 32) * WPAD + k];
                float wz1 = sw[(j0 + 33) * WPAD + k];
                float wn0 = sw[(j0 + 64) * WPAD + k];
                float wn1 = sw[(j0 + 65) * WPAD + k];
                #pragma unroll
                for (int i = 0; i < 8; i++) {
                    acc[i][0] = fmaf(hv[i], wr0, acc[i][0]);
                    acc[i][1] = fmaf(hv[i], wr1, acc[i][1]);
                    acc[i][2] = fmaf(hv[i], wz0, acc[i][2]);
                    acc[i][3] = fmaf(hv[i], wz1, acc[i][3]);
                    acc[i][4] = fmaf(hv[i], wn0, acc[i][4]);
                    acc[i][5] = fmaf(hv[i], wn1, acc[i][5]);
                }
            }
        }

        // Gate phase for this unit pair
        const int u = u0 + j0;
        float Ar0 = sA[u],        Ar1 = sA[u + 1];
        float Az0 = sA[256 + u],  Az1 = sA[257 + u];
        float An0 = sA[512 + u],  An1 = sA[513 + u];
        float Cr0 = sC[u]       + sbh[u],        Cr1 = sC[u + 1]   + sbh[u + 1];
        float Cz0 = sC[256 + u] + sbh[256 + u],  Cz1 = sC[257 + u] + sbh[257 + u];
        float Bn0 = sC[512 + u],  Bn1 = sC[513 + u];
        float bn0 = sbh[512 + u], bn1 = sbh[513 + u];
        float wo0 = swo[u],       wo1 = swo[u + 1];

        #pragma unroll
        for (int ri = 0; ri < 8; ri++) {
            const int rl = ty * 8 + ri;
            const float x = sx[rl];

            float gr0 = fmaf(x, Ar0, Cr0) + acc[ri][0];
            float gz0 = fmaf(x, Az0, Cz0) + acc[ri][2];
            float r0  = 1.0f / (1.0f + expf(-gr0));
            float z0  = 1.0f / (1.0f + expf(-gz0));
            float n0  = tanhf(fmaf(r0, acc[ri][4] + bn0, fmaf(x, An0, Bn0)));
            float ho0 = sh_h[rl * HPAD + u];
            float hn0 = fmaf(z0, ho0 - n0, n0);

            float gr1 = fmaf(x, Ar1, Cr1) + acc[ri][1];
            float gz1 = fmaf(x, Az1, Cz1) + acc[ri][3];
            float r1  = 1.0f / (1.0f + expf(-gr1));
            float z1  = 1.0f / (1.0f + expf(-gz1));
            float n1  = tanhf(fmaf(r1, acc[ri][5] + bn1, fmaf(x, An1, Bn1)));
            float ho1 = sh_h[rl * HPAD + u + 1];
            float hn1 = fmaf(z1, ho1 - n1, n1);

            float2 st; st.x = hn0; st.y = hn1;
            *(float2*)(g_h + (size_t)(row0 + rl) * HD + u) = st;

            // pred partial; reduce over the 16 tx lanes in this half-warp
            float p = hn0 * wo0 + hn1 * wo1;
            #pragma unroll
            for (int o = 8; o > 0; o >>= 1)
                p += __shfl_xor_sync(0xffffffffu, p, o);
            pr[ri] += p;      // valid on all lanes; only tx==0 consumes
        }
    }

    // Epilogue: one lane per half-warp owns rows ty*8..ty*8+7
    if (tx == 0) {
        float bo = b_out[0];
        #pragma unroll
        for (int ri = 0; ri < 8; ri++) {
            int row = row0 + ty * 8 + ri;
            float pred = pr[ri] + bo;
            out[(size_t)row * TSTEPS + t] = pred;
            g_x[row] = pred;
        }
    }
}

// ---------------------------------------------------------------------------
extern "C" void kernel_launch(void* const* d_in, const int* in_sizes, int n_in,
                              void* d_out, int out_size)
{
    const float* enc    = (const float*)d_in[0];
    const float* w_proj = (const float*)d_in[1];
    const float* b_proj = (const float*)d_in[2];
    const float* W_ih   = (const float*)d_in[3];
    const float* b_ih   = (const float*)d_in[4];
    const float* W_hh   = (const float*)d_in[5];
    const float* b_hh   = (const float*)d_in[6];
    const float* w_out  = (const float*)d_in[7];
    const float* b_out  = (const float*)d_in[8];
    float* out = (float*)d_out;

    cudaFuncSetAttribute(step_kernel,
                         cudaFuncAttributeMaxDynamicSharedMemorySize, SMEM_BYTES);

    init_kernel<<<256, 256>>>(enc, w_proj, b_proj, W_ih, b_ih);
    for (int t = 0; t < TSTEPS; t++)
        step_kernel<<<NBLK, 256, SMEM_BYTES>>>(W_hh, b_hh, w_out, b_out, out, t);
}

// round 6
// speedup vs baseline: 1.1642x; 1.1634x over previous
#include <cuda_runtime.h>
#include <math.h>
#include <stdint.h>

// Problem constants
#define NROWS   16384
#define HD      256
#define H3      768
#define TSTEPS  24

// Tiling
#define MTILE   128                  // rows per CTA
#define NBLK    (NROWS / MTILE)      // 128 CTAs
#define UC      16                   // hidden units per chunk
#define NCH     (HD / UC)            // 16 chunks
#define PITCH   260                  // smem pitch (== 4 mod 32 -> conflict-free frags)

// Persistent device state
__device__ float g_h[NROWS * HD];    // hidden state [N,H]
__device__ float g_A[H3];            // W_ih @ w_proj
__device__ float g_C[H3];            // W_ih @ b_proj + b_ih

// smem: h tile [128][260] + W chunk [48][260] + A,C,bh [768]*3 + w_out[256] + x[128]
#define SMEM_FLOATS (MTILE * PITCH + 48 * PITCH + 3 * H3 + HD + MTILE)
#define SMEM_BYTES  (SMEM_FLOATS * 4)

// ---------------------------------------------------------------------------
__global__ void init_kernel(const float* __restrict__ enc,
                            const float* __restrict__ w_proj,
                            const float* __restrict__ b_proj,
                            const float* __restrict__ W_ih,
                            const float* __restrict__ b_ih)
{
    int tid = blockIdx.x * blockDim.x + threadIdx.x;
    int nth = gridDim.x * blockDim.x;
    for (int i = tid; i < NROWS * HD; i += nth) g_h[i] = enc[i];

    int warp = tid >> 5, lane = tid & 31, nwarps = nth >> 5;
    for (int j = warp; j < H3; j += nwarps) {
        float sa = 0.0f, sb = 0.0f;
        for (int k = lane; k < HD; k += 32) {
            float w = W_ih[j * HD + k];
            sa += w * w_proj[k];
            sb += w * b_proj[k];
        }
        #pragma unroll
        for (int o = 16; o > 0; o >>= 1) {
            sa += __shfl_xor_sync(0xffffffffu, sa, o);
            sb += __shfl_xor_sync(0xffffffffu, sb, o);
        }
        if (lane == 0) { g_A[j] = sa; g_C[j] = sb + b_ih[j]; }
    }
}

// ---------------------------------------------------------------------------
// tf32 helpers
// ---------------------------------------------------------------------------
__device__ __forceinline__ void split_tf32(float v, uint32_t& hi, uint32_t& lo)
{
    uint32_t h;
    asm("cvt.rna.tf32.f32 %0, %1;" : "=r"(h) : "f"(v));
    float lf = v - __uint_as_float(h);
    uint32_t l;
    asm("cvt.rna.tf32.f32 %0, %1;" : "=r"(l) : "f"(lf));
    hi = h; lo = l;
}

__device__ __forceinline__ void mma8(float* c, const uint32_t* a,
                                     uint32_t b0, uint32_t b1)
{
    asm volatile(
        "mma.sync.aligned.m16n8k8.row.col.f32.tf32.tf32.f32 "
        "{%0,%1,%2,%3}, {%4,%5,%6,%7}, {%8,%9}, {%0,%1,%2,%3};\n"
        : "+f"(c[0]), "+f"(c[1]), "+f"(c[2]), "+f"(c[3])
        : "r"(a[0]), "r"(a[1]), "r"(a[2]), "r"(a[3]), "r"(b0), "r"(b1));
}

// ---------------------------------------------------------------------------
// Fused decoder: all 24 autoregressive GRU steps in one kernel.
// Row-independent recursion -> no cross-CTA sync. Each CTA owns 128 rows.
// GEMM gh = h @ W_hh^T done with m16n8k8 tf32 mma, 3xTF32 for fp32 accuracy.
// 8 warps; warp w owns rows [w*16, w*16+16). Per chunk: 16 units -> 48 gh
// cols (r,z,n) = 6 n8 tiles -> 24 fp32 accumulators/thread.
// ---------------------------------------------------------------------------
extern "C" __global__ void __launch_bounds__(256, 1)
decode_kernel(const float* __restrict__ W_hh,   // [768,256]
              const float* __restrict__ b_hh,   // [768]
              const float* __restrict__ w_out,  // [256]
              const float* __restrict__ b_out,  // [1]
              float* __restrict__ out)          // [N,24]
{
    extern __shared__ float smem[];
    float* sh  = smem;                   // [128][260] h_old
    float* sw  = sh + MTILE * PITCH;     // [48][260]  W chunk
    float* sA  = sw + 48 * PITCH;        // [768]
    float* sC  = sA + H3;                // [768]
    float* sbh = sC + H3;                // [768]
    float* swo = sbh + H3;               // [256]
    float* sx  = swo + HD;               // [128]

    const int tid  = threadIdx.x;
    const int lane = tid & 31;
    const int wid  = tid >> 5;
    const int g    = lane >> 2;          // groupID 0..7
    const int tg   = lane & 3;           // thread-in-group 0..3
    const int wr   = wid * 16;           // warp row base within tile
    const int row0 = blockIdx.x * MTILE;

    for (int i = tid; i < H3; i += 256) { sA[i] = g_A[i]; sC[i] = g_C[i]; sbh[i] = b_hh[i]; }
    for (int i = tid; i < HD; i += 256) swo[i] = w_out[i];
    if (tid < MTILE) sx[tid] = 0.0f;     // x0 = 0
    const float bo = b_out[0];

    for (int t = 0; t < TSTEPS; t++) {
        __syncthreads();   // prior step's g_h writes + sx writes visible; sh free

        // Stage h_old tile from global (L2-resident)
        {
            const float4* gh4 = (const float4*)(g_h + (size_t)row0 * HD);
            #pragma unroll 4
            for (int idx = tid; idx < MTILE * (HD / 4); idx += 256) {
                int r = idx >> 6, c4 = idx & 63;
                float4 v = gh4[idx];
                float* d = sh + r * PITCH + c4 * 4;
                d[0] = v.x; d[1] = v.y; d[2] = v.z; d[3] = v.w;
            }
        }

        float pr0 = 0.0f, pr1 = 0.0f;    // pred partials for rows wr+g, wr+g+8

        for (int ch = 0; ch < NCH; ch++) {
            const int u0 = ch * UC;
            __syncthreads();  // prior chunk's mma done reading sw; sh staged (ch==0)

            // Stage W chunk: 48 rows = {r,z,n} x 16 units, full K=256
            #pragma unroll 3
            for (int idx = tid; idx < 48 * 64; idx += 256) {
                int lr = idx >> 6, c4 = idx & 63;
                int grow = (lr >> 4) * HD + u0 + (lr & 15);
                float4 v = *(const float4*)(W_hh + (size_t)grow * HD + c4 * 4);
                float* d = sw + lr * PITCH + c4 * 4;
                d[0] = v.x; d[1] = v.y; d[2] = v.z; d[3] = v.w;
            }
            __syncthreads();

            float acc[6][4];
            #pragma unroll
            for (int j = 0; j < 6; j++)
                #pragma unroll
                for (int q = 0; q < 4; q++) acc[j][q] = 0.0f;

            #pragma unroll 2
            for (int ks = 0; ks < 32; ks++) {
                const int k0 = ks * 8;
                // A fragments from h_old
                float a0f = sh[(wr + g)     * PITCH + k0 + tg];
                float a1f = sh[(wr + g + 8) * PITCH + k0 + tg];
                float a2f = sh[(wr + g)     * PITCH + k0 + tg + 4];
                float a3f = sh[(wr + g + 8) * PITCH + k0 + tg + 4];
                uint32_t ah[4], al[4];
                split_tf32(a0f, ah[0], al[0]);
                split_tf32(a1f, ah[1], al[1]);
                split_tf32(a2f, ah[2], al[2]);
                split_tf32(a3f, ah[3], al[3]);

                #pragma unroll
                for (int j = 0; j < 6; j++) {
                    float b0f = sw[(8 * j + g) * PITCH + k0 + tg];
                    float b1f = sw[(8 * j + g) * PITCH + k0 + tg + 4];
                    uint32_t bh0, bl0, bh1, bl1;
                    split_tf32(b0f, bh0, bl0);
                    split_tf32(b1f, bh1, bl1);
                    mma8(acc[j], ah, bh0, bh1);   // hi*hi
                    mma8(acc[j], al, bh0, bh1);   // lo*hi
                    mma8(acc[j], ah, bl0, bl1);   // hi*lo
                }
            }

            // Gate phase: thread owns rows {wr+g, wr+g+8} x units
            // {u0+8hj+2tg, +1} with r/z/n from tiles {hj, 2+hj, 4+hj}
            #pragma unroll
            for (int hj = 0; hj < 2; hj++) {
                const int u = u0 + 8 * hj + 2 * tg;   // first of unit pair
                const float Ar0 = sA[u],       Ar1 = sA[u + 1];
                const float Az0 = sA[256 + u], Az1 = sA[257 + u];
                const float An0 = sA[512 + u], An1 = sA[513 + u];
                const float Cr0 = sC[u]       + sbh[u],       Cr1 = sC[u + 1]   + sbh[u + 1];
                const float Cz0 = sC[256 + u] + sbh[256 + u], Cz1 = sC[257 + u] + sbh[257 + u];
                const float Cn0 = sC[512 + u], Cn1 = sC[513 + u];
                const float bn0 = sbh[512 + u], bn1 = sbh[513 + u];
                const float wo0 = swo[u], wo1 = swo[u + 1];
                #pragma unroll
                for (int rh = 0; rh < 2; rh++) {
                    const int R = wr + g + 8 * rh;
                    const float x = sx[R];

                    float gr0 = fmaf(x, Ar0, Cr0) + acc[hj][2 * rh];
                    float gz0 = fmaf(x, Az0, Cz0) + acc[2 + hj][2 * rh];
                    float r0  = 1.0f / (1.0f + expf(-gr0));
                    float z0  = 1.0f / (1.0f + expf(-gz0));
                    float n0  = tanhf(fmaf(r0, acc[4 + hj][2 * rh] + bn0, fmaf(x, An0, Cn0)));
                    float ho0 = sh[R * PITCH + u];
                    float hn0 = fmaf(z0, ho0 - n0, n0);

                    float gr1 = fmaf(x, Ar1, Cr1) + acc[hj][2 * rh + 1];
                    float gz1 = fmaf(x, Az1, Cz1) + acc[2 + hj][2 * rh + 1];
                    float r1  = 1.0f / (1.0f + expf(-gr1));
                    float z1  = 1.0f / (1.0f + expf(-gz1));
                    float n1  = tanhf(fmaf(r1, acc[4 + hj][2 * rh + 1] + bn1, fmaf(x, An1, Cn1)));
                    float ho1 = sh[R * PITCH + u + 1];
                    float hn1 = fmaf(z1, ho1 - n1, n1);

                    float2 st; st.x = hn0; st.y = hn1;
                    *(float2*)(g_h + (size_t)(row0 + R) * HD + u) = st;

                    float p = fmaf(hn0, wo0, hn1 * wo1);
                    if (rh == 0) pr0 += p; else pr1 += p;
                }
            }
        }

        // pred reduce over the 4 lanes of each quad (tg dimension)
        pr0 += __shfl_xor_sync(0xffffffffu, pr0, 1);
        pr0 += __shfl_xor_sync(0xffffffffu, pr0, 2);
        pr1 += __shfl_xor_sync(0xffffffffu, pr1, 1);
        pr1 += __shfl_xor_sync(0xffffffffu, pr1, 2);

        if (tg == 0) {
            const int R0 = wr + g, R1 = R0 + 8;
            float p0 = pr0 + bo, p1 = pr1 + bo;
            out[(size_t)(row0 + R0) * TSTEPS + t] = p0;
            out[(size_t)(row0 + R1) * TSTEPS + t] = p1;
            sx[R0] = p0;          // next step input (own warp's rows only)
            sx[R1] = p1;
        }
    }
}

// ---------------------------------------------------------------------------
extern "C" void kernel_launch(void* const* d_in, const int* in_sizes, int n_in,
                              void* d_out, int out_size)
{
    const float* enc    = (const float*)d_in[0];
    const float* w_proj = (const float*)d_in[1];
    const float* b_proj = (const float*)d_in[2];
    const float* W_ih   = (const float*)d_in[3];
    const float* b_ih   = (const float*)d_in[4];
    const float* W_hh   = (const float*)d_in[5];
    const float* b_hh   = (const float*)d_in[6];
    const float* w_out  = (const float*)d_in[7];
    const float* b_out  = (const float*)d_in[8];
    float* out = (float*)d_out;

    cudaFuncSetAttribute(decode_kernel,
                         cudaFuncAttributeMaxDynamicSharedMemorySize, SMEM_BYTES);

    init_kernel<<<256, 256>>>(enc, w_proj, b_proj, W_ih, b_ih);
    decode_kernel<<<NBLK, 256, SMEM_BYTES>>>(W_hh, b_hh, w_out, b_out, out);
}

// round 8
// speedup vs baseline: 1.4366x; 1.2339x over previous
#include <cuda_runtime.h>
#include <math.h>
#include <stdint.h>

// Problem constants
#define NROWS   16384
#define HD      256
#define H3      768
#define TSTEPS  24

// Tiling
#define MTILE   128                  // rows per CTA
#define NBLK    (NROWS / MTILE)      // 128 CTAs
#define UC      16                   // hidden units per chunk
#define NCH     (HD / UC)            // 16 chunks
#define PITCH   260                  // h smem pitch (stride%32==4 -> conflict-free)
#define WP      132                  // W half-chunk pitch (128 cols + 4)

// Persistent device state
__device__ float    g_h[NROWS * HD];     // hidden state [N,H]
__device__ float    g_A[H3];             // W_ih @ w_proj
__device__ float    g_C[H3];             // W_ih @ b_proj + b_ih
__device__ uint32_t g_Whi[H3 * HD];      // tf32 hi bits of W_hh
__device__ uint32_t g_Wlo[H3 * HD];      // tf32 lo bits of W_hh

// smem: h[128][260] + swh[48][132] + swl[48][132] + A/C/bh[768]*3 + wo[256]
#define SMEM_FLOATS (MTILE * PITCH + 2 * 48 * WP + 3 * H3 + HD)
#define SMEM_BYTES  (SMEM_FLOATS * 4)

// ---------------------------------------------------------------------------
__device__ __forceinline__ void split_tf32(float v, uint32_t& hi, uint32_t& lo)
{
    uint32_t h;
    asm("cvt.rna.tf32.f32 %0, %1;" : "=r"(h) : "f"(v));
    float lf = v - __uint_as_float(h);
    uint32_t l;
    asm("cvt.rna.tf32.f32 %0, %1;" : "=r"(l) : "f"(lf));
    hi = h; lo = l;
}

__global__ void init_kernel(const float* __restrict__ enc,
                            const float* __restrict__ w_proj,
                            const float* __restrict__ b_proj,
                            const float* __restrict__ W_ih,
                            const float* __restrict__ b_ih,
                            const float* __restrict__ W_hh)
{
    int tid = blockIdx.x * blockDim.x + threadIdx.x;
    int nth = gridDim.x * blockDim.x;
    for (int i = tid; i < NROWS * HD; i += nth) g_h[i] = enc[i];

    // precompute W_hh tf32 hi/lo splits (constant across all steps)
    for (int i = tid; i < H3 * HD; i += nth) {
        uint32_t hi, lo;
        split_tf32(W_hh[i], hi, lo);
        g_Whi[i] = hi;
        g_Wlo[i] = lo;
    }

    int warp = tid >> 5, lane = tid & 31, nwarps = nth >> 5;
    for (int j = warp; j < H3; j += nwarps) {
        float sa = 0.0f, sb = 0.0f;
        for (int k = lane; k < HD; k += 32) {
            float w = W_ih[j * HD + k];
            sa += w * w_proj[k];
            sb += w * b_proj[k];
        }
        #pragma unroll
        for (int o = 16; o > 0; o >>= 1) {
            sa += __shfl_xor_sync(0xffffffffu, sa, o);
            sb += __shfl_xor_sync(0xffffffffu, sb, o);
        }
        if (lane == 0) { g_A[j] = sa; g_C[j] = sb + b_ih[j]; }
    }
}

__device__ __forceinline__ void mma8(float* c, const uint32_t* a,
                                     uint32_t b0, uint32_t b1)
{
    asm volatile(
        "mma.sync.aligned.m16n8k8.row.col.f32.tf32.tf32.f32 "
        "{%0,%1,%2,%3}, {%4,%5,%6,%7}, {%8,%9}, {%0,%1,%2,%3};\n"
        : "+f"(c[0]), "+f"(c[1]), "+f"(c[2]), "+f"(c[3])
        : "r"(a[0]), "r"(a[1]), "r"(a[2]), "r"(a[3]), "r"(b0), "r"(b1));
}

// ---------------------------------------------------------------------------
// Fused decoder: all 24 autoregressive GRU steps in one kernel.
// Each CTA owns 128 rows (row-independent recursion, no cross-CTA sync).
// gh = h @ W_hh^T via m16n8k8 tf32 mma, 3xTF32 (hi*hi + lo*hi + hi*lo).
// W_hh hi/lo are PRE-SPLIT in global; mainloop has zero B-side cvt.
// 8 warps; warp w owns rows [w*16, w*16+16).
// ---------------------------------------------------------------------------
extern "C" __global__ void __launch_bounds__(256, 1)
decode_kernel(const float* __restrict__ b_hh,   // [768]
              const float* __restrict__ w_out,  // [256]
              const float* __restrict__ b_out,  // [1]
              float* __restrict__ out)          // [N,24]
{
    extern __shared__ float smem[];
    float*    sh  = smem;                          // [128][260] h_old
    uint32_t* swh = (uint32_t*)(sh + MTILE * PITCH); // [48][132] W hi (tf32 bits)
    uint32_t* swl = swh + 48 * WP;                 // [48][132] W lo
    float*    sA  = (float*)(swl + 48 * WP);       // [768]
    float*    sC  = sA + H3;                       // [768]
    float*    sbh = sC + H3;                       // [768]
    float*    swo = sbh + H3;                      // [256]

    const int tid  = threadIdx.x;
    const int lane = tid & 31;
    const int wid  = tid >> 5;
    const int g    = lane >> 2;          // groupID 0..7
    const int tg   = lane & 3;           // thread-in-group 0..3
    const int wr   = wid * 16;           // warp row base within tile
    const int row0 = blockIdx.x * MTILE;

    for (int i = tid; i < H3; i += 256) { sA[i] = g_A[i]; sC[i] = g_C[i]; sbh[i] = b_hh[i]; }
    for (int i = tid; i < HD; i += 256) swo[i] = w_out[i];
    const float bo = b_out[0];

    float x0 = 0.0f, x1 = 0.0f;          // step input for rows wr+g, wr+g+8

    for (int t = 0; t < TSTEPS; t++) {
        __syncthreads();   // prior step's gate reads of sh done; g_h writes visible

        // Stage h_old tile from global (L2-resident)
        {
            const float4* gh4 = (const float4*)(g_h + (size_t)row0 * HD);
            #pragma unroll 4
            for (int idx = tid; idx < MTILE * (HD / 4); idx += 256) {
                int r = idx >> 6, c4 = idx & 63;
                float4 v = gh4[idx];
                float* d = sh + r * PITCH + c4 * 4;
                d[0] = v.x; d[1] = v.y; d[2] = v.z; d[3] = v.w;
            }
        }

        float pr0 = 0.0f, pr1 = 0.0f;    // pred partials for rows wr+g, wr+g+8

        for (int ch = 0; ch < NCH; ch++) {
            const int u0 = ch * UC;

            float acc[6][4];
            #pragma unroll
            for (int j = 0; j < 6; j++)
                #pragma unroll
                for (int q = 0; q < 4; q++) acc[j][q] = 0.0f;

            #pragma unroll
            for (int kh = 0; kh < 2; kh++) {
                __syncthreads();  // prior segment's mma done reading sw; sh staged

                // Stage W half-chunk: 48 rows = {r,z,n} x 16 units, K cols
                // [kh*128, kh*128+128), hi + lo, as uint4
                {
                    const uint4* Wh4 = (const uint4*)g_Whi;
                    const uint4* Wl4 = (const uint4*)g_Wlo;
                    #pragma unroll 6
                    for (int idx = tid; idx < 48 * 32; idx += 256) {
                        int lr = idx >> 5, c4 = idx & 31;
                        int grow = (lr >> 4) * HD + u0 + (lr & 15);
                        int gsrc = grow * 64 + kh * 32 + c4;
                        uint4 vh = Wh4[gsrc];
                        uint4 vl = Wl4[gsrc];
                        uint32_t* dh = swh + lr * WP + c4 * 4;
                        uint32_t* dl = swl + lr * WP + c4 * 4;
                        dh[0] = vh.x; dh[1] = vh.y; dh[2] = vh.z; dh[3] = vh.w;
                        dl[0] = vl.x; dl[1] = vl.y; dl[2] = vl.z; dl[3] = vl.w;
                    }
                }
                __syncthreads();

                #pragma unroll 2
                for (int ks = 0; ks < 16; ks++) {
                    const int kk = ks * 8;            // col within half
                    const int k0 = kh * 128 + kk;     // col within full K
                    float a0f = sh[(wr + g)     * PITCH + k0 + tg];
                    float a1f = sh[(wr + g + 8) * PITCH + k0 + tg];
                    float a2f = sh[(wr + g)     * PITCH + k0 + tg + 4];
                    float a3f = sh[(wr + g + 8) * PITCH + k0 + tg + 4];
                    uint32_t ah[4], al[4];
                    split_tf32(a0f, ah[0], al[0]);
                    split_tf32(a1f, ah[1], al[1]);
                    split_tf32(a2f, ah[2], al[2]);
                    split_tf32(a3f, ah[3], al[3]);

                    #pragma unroll
                    for (int j = 0; j < 6; j++) {
                        const int wb = (8 * j + g) * WP + kk + tg;
                        uint32_t bh0 = swh[wb], bh1 = swh[wb + 4];
                        uint32_t bl0 = swl[wb], bl1 = swl[wb + 4];
                        mma8(acc[j], ah, bh0, bh1);   // hi*hi
                        mma8(acc[j], al, bh0, bh1);   // lo*hi
                        mma8(acc[j], ah, bl0, bl1);   // hi*lo
                    }
                }
            }

            // Gate phase: thread owns rows {wr+g, wr+g+8} x unit pairs
            #pragma unroll
            for (int hj = 0; hj < 2; hj++) {
                const int u = u0 + 8 * hj + 2 * tg;   // first of unit pair
                const float Ar0 = sA[u],       Ar1 = sA[u + 1];
                const float Az0 = sA[256 + u], Az1 = sA[257 + u];
                const float An0 = sA[512 + u], An1 = sA[513 + u];
                const float Cr0 = sC[u]       + sbh[u],       Cr1 = sC[u + 1]   + sbh[u + 1];
                const float Cz0 = sC[256 + u] + sbh[256 + u], Cz1 = sC[257 + u] + sbh[257 + u];
                const float Cn0 = sC[512 + u], Cn1 = sC[513 + u];
                const float bn0 = sbh[512 + u], bn1 = sbh[513 + u];
                const float wo0 = swo[u], wo1 = swo[u + 1];
                #pragma unroll
                for (int rh = 0; rh < 2; rh++) {
                    const int R = wr + g + 8 * rh;
                    const float x = (rh == 0) ? x0 : x1;

                    float gr0 = fmaf(x, Ar0, Cr0) + acc[hj][2 * rh];
                    float gz0 = fmaf(x, Az0, Cz0) + acc[2 + hj][2 * rh];
                    float r0  = 1.0f / (1.0f + expf(-gr0));
                    float z0  = 1.0f / (1.0f + expf(-gz0));
                    float n0  = tanhf(fmaf(r0, acc[4 + hj][2 * rh] + bn0, fmaf(x, An0, Cn0)));
                    float ho0 = sh[R * PITCH + u];
                    float hn0 = fmaf(z0, ho0 - n0, n0);

                    float gr1 = fmaf(x, Ar1, Cr1) + acc[hj][2 * rh + 1];
                    float gz1 = fmaf(x, Az1, Cz1) + acc[2 + hj][2 * rh + 1];
                    float r1  = 1.0f / (1.0f + expf(-gr1));
                    float z1  = 1.0f / (1.0f + expf(-gz1));
                    float n1  = tanhf(fmaf(r1, acc[4 + hj][2 * rh + 1] + bn1, fmaf(x, An1, Cn1)));
                    float ho1 = sh[R * PITCH + u + 1];
                    float hn1 = fmaf(z1, ho1 - n1, n1);

                    float2 st; st.x = hn0; st.y = hn1;
                    *(float2*)(g_h + (size_t)(row0 + R) * HD + u) = st;

                    float p = fmaf(hn0, wo0, hn1 * wo1);
                    if (rh == 0) pr0 += p; else pr1 += p;
                }
            }
        }

        // pred reduce over the 4 lanes of each quad (tg dimension);
        // result valid on ALL quad lanes -> next x lives in registers
        pr0 += __shfl_xor_sync(0xffffffffu, pr0, 1);
        pr0 += __shfl_xor_sync(0xffffffffu, pr0, 2);
        pr1 += __shfl_xor_sync(0xffffffffu, pr1, 1);
        pr1 += __shfl_xor_sync(0xffffffffu, pr1, 2);

        x0 = pr0 + bo;
        x1 = pr1 + bo;

        if (tg == 0) {
            const int R0 = wr + g, R1 = R0 + 8;
            out[(size_t)(row0 + R0) * TSTEPS + t] = x0;
            out[(size_t)(row0 + R1) * TSTEPS + t] = x1;
        }
    }
}

// ---------------------------------------------------------------------------
extern "C" void kernel_launch(void* const* d_in, const int* in_sizes, int n_in,
                              void* d_out, int out_size)
{
    const float* enc    = (const float*)d_in[0];
    const float* w_proj = (const float*)d_in[1];
    const float* b_proj = (const float*)d_in[2];
    const float* W_ih   = (const float*)d_in[3];
    const float* b_ih   = (const float*)d_in[4];
    const float* W_hh   = (const float*)d_in[5];
    const float* b_hh   = (const float*)d_in[6];
    const float* w_out  = (const float*)d_in[7];
    const float* b_out  = (const float*)d_in[8];
    float* out = (float*)d_out;

    cudaFuncSetAttribute(decode_kernel,
                         cudaFuncAttributeMaxDynamicSharedMemorySize, SMEM_BYTES);

    init_kernel<<<256, 256>>>(enc, w_proj, b_proj, W_ih, b_ih, W_hh);
    decode_kernel<<<NBLK, 256, SMEM_BYTES>>>(b_hh, w_out, b_out, out);
}

// round 10
// speedup vs baseline: 1.8709x; 1.3024x over previous
#include <cuda_runtime.h>
#include <math.h>
#include <stdint.h>

// Problem constants
#define NROWS   16384
#define HD      256
#define H3      768
#define TSTEPS  24

// Tiling
#define MTILE   128                  // rows per CTA
#define NBLK    (NROWS / MTILE)      // 128 CTAs
#define UC      32                   // hidden units per chunk
#define NCH     (HD / UC)            // 8 chunks
#define NSEG    64                   // 8 chunks x 8 K-segments of 32
#define PITCH   260                  // h smem pitch (stride%32==4, conflict-free)
#define WP      40                   // W segment row pitch (32 cols + pad; LDS.64-conflict-free)
#define WROWS   96                   // 3 gates x 32 units
#define WSEGW   (WROWS * WP)         // 3840 words per (hi|lo) segment
#define WBUFW   (2 * WSEGW)          // 7680 words per buffer (hi+lo)

// Persistent device state
__device__ float    g_h[NROWS * HD];        // hidden state [N,H]
__device__ float    g_A[H3];                // W_ih @ w_proj
__device__ float    g_C[H3];                // W_ih @ b_proj + b_ih
// W_hh pre-split tf32 hi/lo, chunk-major [8][96][256], cols pair-permuted
__device__ uint32_t g_Wp_hi[NCH * WROWS * HD];
__device__ uint32_t g_Wp_lo[NCH * WROWS * HD];

// smem words: sh[128*260] + 2 W buffers [2*7680] + A/C/bh[768*3] + wo[256]
#define SH_W    (MTILE * PITCH)              // 33280
#define SWB_W   SH_W                         // W buffers start
#define SA_W    (SWB_W + 2 * WBUFW)          // 48640
#define SMEM_WORDS (SA_W + 3 * H3 + HD)      // 51200
#define SMEM_BYTES (SMEM_WORDS * 4)          // 204800

// ---------------------------------------------------------------------------
__device__ __forceinline__ void split_tf32(float v, uint32_t& hi, uint32_t& lo)
{
    uint32_t h;
    asm("cvt.rna.tf32.f32 %0, %1;" : "=r"(h) : "f"(v));
    float lf = v - __uint_as_float(h);
    uint32_t l;
    asm("cvt.rna.tf32.f32 %0, %1;" : "=r"(l) : "f"(lf));
    hi = h; lo = l;
}

__global__ void init_kernel(const float* __restrict__ enc,
                            const float* __restrict__ w_proj,
                            const float* __restrict__ b_proj,
                            const float* __restrict__ W_ih,
                            const float* __restrict__ b_ih,
                            const float* __restrict__ W_hh)
{
    int tid = blockIdx.x * blockDim.x + threadIdx.x;
    int nth = gridDim.x * blockDim.x;
    for (int i = tid; i < NROWS * HD; i += nth) g_h[i] = enc[i];

    // Pre-split + reorder W_hh: chunk-major rows, pair-permuted cols.
    // src row = gate*256 + unit; chunk = unit>>5; lr = gate*32 + (unit&31)
    // col k -> (k&~7) | (2*(k&3) + ((k>>2)&1))   (pairs (tg, tg+4) adjacent)
    for (int i = tid; i < H3 * HD; i += nth) {
        int row  = i >> 8;
        int k    = i & 255;
        int gate = row >> 8;
        int unit = row & 255;
        int ch   = unit >> 5;
        int lr   = (gate << 5) | (unit & 31);
        int dcol = (k & ~7) | (2 * (k & 3) + ((k >> 2) & 1));
        int dst  = ((ch * WROWS) + lr) * HD + dcol;
        uint32_t hi, lo;
        split_tf32(W_hh[i], hi, lo);
        g_Wp_hi[dst] = hi;
        g_Wp_lo[dst] = lo;
    }

    int warp = tid >> 5, lane = tid & 31, nwarps = nth >> 5;
    for (int j = warp; j < H3; j += nwarps) {
        float sa = 0.0f, sb = 0.0f;
        for (int k = lane; k < HD; k += 32) {
            float w = W_ih[j * HD + k];
            sa += w * w_proj[k];
            sb += w * b_proj[k];
        }
        #pragma unroll
        for (int o = 16; o > 0; o >>= 1) {
            sa += __shfl_xor_sync(0xffffffffu, sa, o);
            sb += __shfl_xor_sync(0xffffffffu, sb, o);
        }
        if (lane == 0) { g_A[j] = sa; g_C[j] = sb + b_ih[j]; }
    }
}

// ---------------------------------------------------------------------------
__device__ __forceinline__ void mma8(float* c, const uint32_t* a,
                                     uint32_t b0, uint32_t b1)
{
    asm volatile(
        "mma.sync.aligned.m16n8k8.row.col.f32.tf32.tf32.f32 "
        "{%0,%1,%2,%3}, {%4,%5,%6,%7}, {%8,%9}, {%0,%1,%2,%3};\n"
        : "+f"(c[0]), "+f"(c[1]), "+f"(c[2]), "+f"(c[3])
        : "r"(a[0]), "r"(a[1]), "r"(a[2]), "r"(a[3]), "r"(b0), "r"(b1));
}

__device__ __forceinline__ void cp16(uint32_t dst_smem, const void* src)
{
    asm volatile("cp.async.cg.shared.global [%0], [%1], 16;\n"
                 :: "r"(dst_smem), "l"(src));
}

__device__ __forceinline__ float fast_sig(float x)
{
    float e, r;
    asm("ex2.approx.ftz.f32 %0, %1;" : "=f"(e) : "f"(-1.4426950408889634f * x));
    asm("rcp.approx.ftz.f32 %0, %1;" : "=f"(r) : "f"(1.0f + e));
    return r;
}
__device__ __forceinline__ float fast_tanh(float x)
{
    float e, r;
    asm("ex2.approx.ftz.f32 %0, %1;" : "=f"(e) : "f"(-2.8853900817779268f * x));
    asm("rcp.approx.ftz.f32 %0, %1;" : "=f"(r) : "f"(1.0f + e));
    return fmaf(2.0f, r, -1.0f);
}

// ---------------------------------------------------------------------------
// Fused decoder: all 24 autoregressive GRU steps in one kernel.
// W streamed as 64 segments/step of [96 x 32] hi+lo via cp.async,
// double-buffered; the pipeline wraps across steps (W is step-invariant).
// 8 warps; warp w owns rows [w*16, w*16+16). Per chunk: 32 units -> 96 gh
// cols (r,z,n) = 12 n8 tiles -> 48 fp32 accumulators/thread. 3xTF32.
// ---------------------------------------------------------------------------
extern "C" __global__ void __launch_bounds__(256, 1)
decode_kernel(const float* __restrict__ b_hh,   // [768]
              const float* __restrict__ w_out,  // [256]
              const float* __restrict__ b_out,  // [1]
              float* __restrict__ out)          // [N,24]
{
    extern __shared__ float smem[];
    float*    sh  = smem;                        // [128][260] h_old
    uint32_t* swb = (uint32_t*)smem + SWB_W;     // 2 x [hi 96x40 | lo 96x40]
    float*    sA  = smem + SA_W;                 // [768]
    float*    sC  = sA + H3;                     // [768]
    float*    sbh = sC + H3;                     // [768]
    float*    swo = sbh + H3;                    // [256]

    const int tid  = threadIdx.x;
    const int lane = tid & 31;
    const int wid  = tid >> 5;
    const int g    = lane >> 2;          // groupID 0..7
    const int tg   = lane & 3;           // thread-in-group 0..3
    const int wr   = wid * 16;           // warp row base within tile
    const int row0 = blockIdx.x * MTILE;

    const uint32_t smem_base = (uint32_t)__cvta_generic_to_shared(smem);
    const uint32_t swb_bytes = smem_base + SWB_W * 4;

    for (int i = tid; i < H3; i += 256) { sA[i] = g_A[i]; sC[i] = g_C[i]; sbh[i] = b_hh[i]; }
    for (int i = tid; i < HD; i += 256) swo[i] = w_out[i];
    const float bo = b_out[0];

    // --- prefetch one W segment (6 x cp16 per thread + commit) ---
    // Segment = [96 rows x 32 cols] of hi and lo. 768 (lr,c4) slots; each
    // cp16 moves 4 words. Source word index = row*HD + q*32 + c4*4.
    auto prefetch_seg = [&](int s) {
        const int ch  = s >> 3, q = s & 7, buf = s & 1;
        const uint32_t dbase = swb_bytes + (uint32_t)(buf * WBUFW) * 4;
        #pragma unroll
        for (int i = 0; i < 3; i++) {
            int e  = i * 256 + tid;          // 0..767
            int lr = e >> 3, c4 = e & 7;
            int gsrc = ((ch * WROWS) + lr) * HD + q * 32 + c4 * 4;
            uint32_t dst = dbase + (uint32_t)(lr * WP + c4 * 4) * 4;
            cp16(dst,                 g_Wp_hi + gsrc);
            cp16(dst + WSEGW * 4,     g_Wp_lo + gsrc);
        }
        asm volatile("cp.async.commit_group;\n");
    };

    float x0 = 0.0f, x1 = 0.0f;          // step input for rows wr+g, wr+g+8

    prefetch_seg(0);                     // prime the pipeline

    for (int t = 0; t < TSTEPS; t++) {
        // Stage h_old tile from global (L2-resident); overlaps seg prefetch
        {
            const float4* gh4 = (const float4*)(g_h + (size_t)row0 * HD);
            #pragma unroll 4
            for (int idx = tid; idx < MTILE * (HD / 4); idx += 256) {
                int r = idx >> 6, c4 = idx & 63;
                float4 v = gh4[idx];
                float* d = sh + r * PITCH + c4 * 4;
                d[0] = v.x; d[1] = v.y; d[2] = v.z; d[3] = v.w;
            }
        }

        float pr0 = 0.0f, pr1 = 0.0f;    // pred partials
        float acc[12][4];

        for (int s = 0; s < NSEG; s++) {
            const int ch = s >> 3, q = s & 7, buf = s & 1;

            prefetch_seg((s + 1) & (NSEG - 1));   // wraps into next step

            asm volatile("cp.async.wait_group 1;\n");
            __syncthreads();             // seg data + (s==0) h tile visible

            if (q == 0) {
                #pragma unroll
                for (int j = 0; j < 12; j++)
                    #pragma unroll
                    for (int c = 0; c < 4; c++) acc[j][c] = 0.0f;
            }

            const uint32_t* hiP = swb + buf * WBUFW;
            const uint32_t* loP = hiP + WSEGW;

            #pragma unroll
            for (int ks = 0; ks < 4; ks++) {
                const int k0 = q * 32 + ks * 8;
                float a0f = sh[(wr + g)     * PITCH + k0 + tg];
                float a1f = sh[(wr + g + 8) * PITCH + k0 + tg];
                float a2f = sh[(wr + g)     * PITCH + k0 + tg + 4];
                float a3f = sh[(wr + g + 8) * PITCH + k0 + tg + 4];
                uint32_t ah[4], al[4];
                split_tf32(a0f, ah[0], al[0]);
                split_tf32(a1f, ah[1], al[1]);
                split_tf32(a2f, ah[2], al[2]);
                split_tf32(a3f, ah[3], al[3]);

                #pragma unroll
                for (int j = 0; j < 12; j++) {
                    const int wb = (8 * j + g) * WP + ks * 8 + 2 * tg;
                    uint2 bh = *(const uint2*)(hiP + wb);
                    uint2 bl = *(const uint2*)(loP + wb);
                    mma8(acc[j], ah, bh.x, bh.y);   // hi*hi
                    mma8(acc[j], al, bh.x, bh.y);   // lo*hi
                    mma8(acc[j], ah, bl.x, bl.y);   // hi*lo
                }
            }

            if (q == 7) {
                // Gate phase for chunk ch: thread owns rows {wr+g, wr+g+8}
                // x unit pairs {u0 + jm*8 + 2tg, +1}; r/z/n tiles {jm,4+jm,8+jm}
                const int u0 = ch * UC;
                #pragma unroll
                for (int jm = 0; jm < 4; jm++) {
                    const int u = u0 + jm * 8 + 2 * tg;
                    const float Ar0 = sA[u],       Ar1 = sA[u + 1];
                    const float Az0 = sA[256 + u], Az1 = sA[257 + u];
                    const float An0 = sA[512 + u], An1 = sA[513 + u];
                    const float Cr0 = sC[u]       + sbh[u],       Cr1 = sC[u + 1]   + sbh[u + 1];
                    const float Cz0 = sC[256 + u] + sbh[256 + u], Cz1 = sC[257 + u] + sbh[257 + u];
                    const float Cn0 = sC[512 + u], Cn1 = sC[513 + u];
                    const float bn0 = sbh[512 + u], bn1 = sbh[513 + u];
                    const float wo0 = swo[u], wo1 = swo[u + 1];
                    #pragma unroll
                    for (int rh = 0; rh < 2; rh++) {
                        const int R = wr + g + 8 * rh;
                        const float x = (rh == 0) ? x0 : x1;

                        float gr0 = fmaf(x, Ar0, Cr0) + acc[jm][2 * rh];
                        float gz0 = fmaf(x, Az0, Cz0) + acc[4 + jm][2 * rh];
                        float r0  = fast_sig(gr0);
                        float z0  = fast_sig(gz0);
                        float n0  = fast_tanh(fmaf(r0, acc[8 + jm][2 * rh] + bn0, fmaf(x, An0, Cn0)));
                        float ho0 = sh[R * PITCH + u];
                        float hn0 = fmaf(z0, ho0 - n0, n0);

                        float gr1 = fmaf(x, Ar1, Cr1) + acc[jm][2 * rh + 1];
                        float gz1 = fmaf(x, Az1, Cz1) + acc[4 + jm][2 * rh + 1];
                        float r1  = fast_sig(gr1);
                        float z1  = fast_sig(gz1);
                        float n1  = fast_tanh(fmaf(r1, acc[8 + jm][2 * rh + 1] + bn1, fmaf(x, An1, Cn1)));
                        float ho1 = sh[R * PITCH + u + 1];
                        float hn1 = fmaf(z1, ho1 - n1, n1);

                        float2 st; st.x = hn0; st.y = hn1;
                        *(float2*)(g_h + (size_t)(row0 + R) * HD + u) = st;

                        float p = fmaf(hn0, wo0, hn1 * wo1);
                        if (rh == 0) pr0 += p; else pr1 += p;
                    }
                }
            }

            __syncthreads();   // protect buf[cur] before next iter's prefetch
        }

        // pred reduce over quad lanes; result valid on all 4 -> x in regs
        pr0 += __shfl_xor_sync(0xffffffffu, pr0, 1);
        pr0 += __shfl_xor_sync(0xffffffffu, pr0, 2);
        pr1 += __shfl_xor_sync(0xffffffffu, pr1, 1);
        pr1 += __shfl_xor_sync(0xffffffffu, pr1, 2);

        x0 = pr0 + bo;
        x1 = pr1 + bo;

        if (tg == 0) {
            const int R0 = wr + g, R1 = R0 + 8;
            out[(size_t)(row0 + R0) * TSTEPS + t] = x0;
            out[(size_t)(row0 + R1) * TSTEPS + t] = x1;
        }
    }
}

// ---------------------------------------------------------------------------
extern "C" void kernel_launch(void* const* d_in, const int* in_sizes, int n_in,
                              void* d_out, int out_size)
{
    const float* enc    = (const float*)d_in[0];
    const float* w_proj = (const float*)d_in[1];
    const float* b_proj = (const float*)d_in[2];
    const float* W_ih   = (const float*)d_in[3];
    const float* b_ih   = (const float*)d_in[4];
    const float* W_hh   = (const float*)d_in[5];
    const float* b_hh   = (const float*)d_in[6];
    const float* w_out  = (const float*)d_in[7];
    const float* b_out  = (const float*)d_in[8];
    float* out = (float*)d_out;

    cudaFuncSetAttribute(decode_kernel,
                         cudaFuncAttributeMaxDynamicSharedMemorySize, SMEM_BYTES);

    init_kernel<<<256, 256>>>(enc, w_proj, b_proj, W_ih, b_ih, W_hh);
    decode_kernel<<<NBLK, 256, SMEM_BYTES>>>(b_hh, w_out, b_out, out);
}

// round 12
// speedup vs baseline: 2.3764x; 1.2702x over previous
#include <cuda_runtime.h>
#include <math.h>
#include <stdint.h>

// Problem constants
#define NROWS   16384
#define HD      256
#define H3      768
#define TSTEPS  24

// Tiling
#define MTILE   128                  // rows per CTA
#define NBLK    (NROWS / MTILE)      // 128 CTAs
#define UC      32                   // hidden units per chunk
#define NCH     (HD / UC)            // 8 chunks
#define NSEG    64                   // 8 chunks x 8 K-segments of 32
#define PITCH   260                  // h smem pitch (stride%32==4, conflict-free)
#define WP      40                   // W segment row pitch (32 cols + pad; LDS.64-conflict-free)
#define WROWS   96                   // 3 gates x 32 units
#define WSEGW   (WROWS * WP)         // 3840 words per (hi|lo) segment
#define WBUFW   (2 * WSEGW)          // 7680 words per buffer (hi+lo)

// Persistent device state
__device__ float    g_h[NROWS * HD];        // hidden state [N,H]
__device__ float    g_A[H3];                // W_ih @ w_proj
__device__ float    g_C[H3];                // W_ih @ b_proj + b_ih
// W_hh pre-split tf32 hi/lo, chunk-major [8][96][256], cols pair-permuted
__device__ uint32_t g_Wp_hi[NCH * WROWS * HD];
__device__ uint32_t g_Wp_lo[NCH * WROWS * HD];

// smem words: sh[128*260] + 2 W buffers [2*7680] + A/C/bh[768*3] + wo[256]
#define SH_W    (MTILE * PITCH)              // 33280
#define SWB_W   SH_W                         // W buffers start
#define SA_W    (SWB_W + 2 * WBUFW)          // 48640
#define SMEM_WORDS (SA_W + 3 * H3 + HD)      // 51200
#define SMEM_BYTES (SMEM_WORDS * 4)          // 204800

// ---------------------------------------------------------------------------
__device__ __forceinline__ void split_tf32(float v, uint32_t& hi, uint32_t& lo)
{
    uint32_t h;
    asm("cvt.rna.tf32.f32 %0, %1;" : "=r"(h) : "f"(v));
    float lf = v - __uint_as_float(h);
    uint32_t l;
    asm("cvt.rna.tf32.f32 %0, %1;" : "=r"(l) : "f"(lf));
    hi = h; lo = l;
}

__device__ __forceinline__ uint32_t cvt_tf32(float v)
{
    uint32_t h;
    asm("cvt.rna.tf32.f32 %0, %1;" : "=r"(h) : "f"(v));
    return h;
}

__global__ void init_kernel(const float* __restrict__ enc,
                            const float* __restrict__ w_proj,
                            const float* __restrict__ b_proj,
                            const float* __restrict__ W_ih,
                            const float* __restrict__ b_ih,
                            const float* __restrict__ W_hh)
{
    int tid = blockIdx.x * blockDim.x + threadIdx.x;
    int nth = gridDim.x * blockDim.x;
    for (int i = tid; i < NROWS * HD; i += nth) g_h[i] = enc[i];

    // Pre-split + reorder W_hh: chunk-major rows, pair-permuted cols.
    // src row = gate*256 + unit; chunk = unit>>5; lr = gate*32 + (unit&31)
    // col k -> (k&~7) | (2*(k&3) + ((k>>2)&1))   (pairs (tg, tg+4) adjacent)
    for (int i = tid; i < H3 * HD; i += nth) {
        int row  = i >> 8;
        int k    = i & 255;
        int gate = row >> 8;
        int unit = row & 255;
        int ch   = unit >> 5;
        int lr   = (gate << 5) | (unit & 31);
        int dcol = (k & ~7) | (2 * (k & 3) + ((k >> 2) & 1));
        int dst  = ((ch * WROWS) + lr) * HD + dcol;
        uint32_t hi, lo;
        split_tf32(W_hh[i], hi, lo);
        g_Wp_hi[dst] = hi;
        g_Wp_lo[dst] = lo;
    }

    int warp = tid >> 5, lane = tid & 31, nwarps = nth >> 5;
    for (int j = warp; j < H3; j += nwarps) {
        float sa = 0.0f, sb = 0.0f;
        for (int k = lane; k < HD; k += 32) {
            float w = W_ih[j * HD + k];
            sa += w * w_proj[k];
            sb += w * b_proj[k];
        }
        #pragma unroll
        for (int o = 16; o > 0; o >>= 1) {
            sa += __shfl_xor_sync(0xffffffffu, sa, o);
            sb += __shfl_xor_sync(0xffffffffu, sb, o);
        }
        if (lane == 0) { g_A[j] = sa; g_C[j] = sb + b_ih[j]; }
    }
}

// ---------------------------------------------------------------------------
__device__ __forceinline__ void mma8(float* c, const uint32_t* a,
                                     uint32_t b0, uint32_t b1)
{
    asm volatile(
        "mma.sync.aligned.m16n8k8.row.col.f32.tf32.tf32.f32 "
        "{%0,%1,%2,%3}, {%4,%5,%6,%7}, {%8,%9}, {%0,%1,%2,%3};\n"
        : "+f"(c[0]), "+f"(c[1]), "+f"(c[2]), "+f"(c[3])
        : "r"(a[0]), "r"(a[1]), "r"(a[2]), "r"(a[3]), "r"(b0), "r"(b1));
}

__device__ __forceinline__ void cp16(uint32_t dst_smem, const void* src)
{
    asm volatile("cp.async.cg.shared.global [%0], [%1], 16;\n"
                 :: "r"(dst_smem), "l"(src));
}

__device__ __forceinline__ float fast_sig(float x)
{
    float e, r;
    asm("ex2.approx.ftz.f32 %0, %1;" : "=f"(e) : "f"(-1.4426950408889634f * x));
    asm("rcp.approx.ftz.f32 %0, %1;" : "=f"(r) : "f"(1.0f + e));
    return r;
}
__device__ __forceinline__ float fast_tanh(float x)
{
    float e, r;
    asm("ex2.approx.ftz.f32 %0, %1;" : "=f"(e) : "f"(-2.8853900817779268f * x));
    asm("rcp.approx.ftz.f32 %0, %1;" : "=f"(r) : "f"(1.0f + e));
    return fmaf(2.0f, r, -1.0f);
}

// ---------------------------------------------------------------------------
// Fused decoder: all 24 autoregressive GRU steps in one kernel.
// W streamed as 64 segments/step of [96 x 32] hi+lo via cp.async,
// double-buffered; pipeline wraps across steps (W is step-invariant).
// Precision scheme: a_tf32 * (b_hi + b_lo)  -> 2 MMAs per k-octet per tile.
// B error ~2^-22 (hi+lo), A error 2^-11 -> gh rel err ~2.8e-4 rms, gates
// compress further; threshold is 1e-3.
// 8 warps; warp w owns rows [w*16, w*16+16). Per chunk: 32 units -> 96 gh
// cols (r,z,n) = 12 n8 tiles -> 48 fp32 accumulators/thread.
// ---------------------------------------------------------------------------
extern "C" __global__ void __launch_bounds__(256, 1)
decode_kernel(const float* __restrict__ b_hh,   // [768]
              const float* __restrict__ w_out,  // [256]
              const float* __restrict__ b_out,  // [1]
              float* __restrict__ out)          // [N,24]
{
    extern __shared__ float smem[];
    float*    sh  = smem;                        // [128][260] h_old
    uint32_t* swb = (uint32_t*)smem + SWB_W;     // 2 x [hi 96x40 | lo 96x40]
    float*    sA  = smem + SA_W;                 // [768]
    float*    sC  = sA + H3;                     // [768]
    float*    sbh = sC + H3;                     // [768]
    float*    swo = sbh + H3;                    // [256]

    const int tid  = threadIdx.x;
    const int lane = tid & 31;
    const int wid  = tid >> 5;
    const int g    = lane >> 2;          // groupID 0..7
    const int tg   = lane & 3;           // thread-in-group 0..3
    const int wr   = wid * 16;           // warp row base within tile
    const int row0 = blockIdx.x * MTILE;

    const uint32_t smem_base = (uint32_t)__cvta_generic_to_shared(smem);
    const uint32_t swb_bytes = smem_base + SWB_W * 4;

    for (int i = tid; i < H3; i += 256) { sA[i] = g_A[i]; sC[i] = g_C[i]; sbh[i] = b_hh[i]; }
    for (int i = tid; i < HD; i += 256) swo[i] = w_out[i];
    const float bo = b_out[0];

    // --- prefetch one W segment (6 x cp16 per thread + commit) ---
    // Segment = [96 rows x 32 cols] of hi and lo. 768 (lr,c4) slots; each
    // cp16 moves 4 words. Source word index = row*HD + q*32 + c4*4.
    auto prefetch_seg = [&](int s) {
        const int ch  = s >> 3, q = s & 7, buf = s & 1;
        const uint32_t dbase = swb_bytes + (uint32_t)(buf * WBUFW) * 4;
        #pragma unroll
        for (int i = 0; i < 3; i++) {
            int e  = i * 256 + tid;          // 0..767
            int lr = e >> 3, c4 = e & 7;
            int gsrc = ((ch * WROWS) + lr) * HD + q * 32 + c4 * 4;
            uint32_t dst = dbase + (uint32_t)(lr * WP + c4 * 4) * 4;
            cp16(dst,                 g_Wp_hi + gsrc);
            cp16(dst + WSEGW * 4,     g_Wp_lo + gsrc);
        }
        asm volatile("cp.async.commit_group;\n");
    };

    float x0 = 0.0f, x1 = 0.0f;          // step input for rows wr+g, wr+g+8

    prefetch_seg(0);                     // prime the pipeline

    for (int t = 0; t < TSTEPS; t++) {
        // Stage h_old tile from global (L2-resident); overlaps seg prefetch
        {
            const float4* gh4 = (const float4*)(g_h + (size_t)row0 * HD);
            #pragma unroll 4
            for (int idx = tid; idx < MTILE * (HD / 4); idx += 256) {
                int r = idx >> 6, c4 = idx & 63;
                float4 v = gh4[idx];
                float* d = sh + r * PITCH + c4 * 4;
                d[0] = v.x; d[1] = v.y; d[2] = v.z; d[3] = v.w;
            }
        }

        float pr0 = 0.0f, pr1 = 0.0f;    // pred partials
        float acc[12][4];

        for (int s = 0; s < NSEG; s++) {
            const int ch = s >> 3, q = s & 7, buf = s & 1;

            prefetch_seg((s + 1) & (NSEG - 1));   // wraps into next step

            asm volatile("cp.async.wait_group 1;\n");
            __syncthreads();             // seg data + (s==0) h tile visible

            if (q == 0) {
                #pragma unroll
                for (int j = 0; j < 12; j++)
                    #pragma unroll
                    for (int c = 0; c < 4; c++) acc[j][c] = 0.0f;
            }

            const uint32_t* hiP = swb + buf * WBUFW;
            const uint32_t* loP = hiP + WSEGW;

            #pragma unroll
            for (int ks = 0; ks < 4; ks++) {
                const int k0 = q * 32 + ks * 8;
                // A fragments: single tf32 cvt (precision lives on B side)
                uint32_t ua[4];
                ua[0] = cvt_tf32(sh[(wr + g)     * PITCH + k0 + tg]);
                ua[1] = cvt_tf32(sh[(wr + g + 8) * PITCH + k0 + tg]);
                ua[2] = cvt_tf32(sh[(wr + g)     * PITCH + k0 + tg + 4]);
                ua[3] = cvt_tf32(sh[(wr + g + 8) * PITCH + k0 + tg + 4]);

                #pragma unroll
                for (int j = 0; j < 12; j++) {
                    const int wb = (8 * j + g) * WP + ks * 8 + 2 * tg;
                    uint2 bh = *(const uint2*)(hiP + wb);
                    uint2 bl = *(const uint2*)(loP + wb);
                    mma8(acc[j], ua, bh.x, bh.y);   // a * b_hi
                    mma8(acc[j], ua, bl.x, bl.y);   // a * b_lo
                }
            }

            if (q == 7) {
                // Gate phase for chunk ch: thread owns rows {wr+g, wr+g+8}
                // x unit pairs {u0 + jm*8 + 2tg, +1}; r/z/n tiles {jm,4+jm,8+jm}
                const int u0 = ch * UC;
                #pragma unroll
                for (int jm = 0; jm < 4; jm++) {
                    const int u = u0 + jm * 8 + 2 * tg;
                    const float Ar0 = sA[u],       Ar1 = sA[u + 1];
                    const float Az0 = sA[256 + u], Az1 = sA[257 + u];
                    const float An0 = sA[512 + u], An1 = sA[513 + u];
                    const float Cr0 = sC[u]       + sbh[u],       Cr1 = sC[u + 1]   + sbh[u + 1];
                    const float Cz0 = sC[256 + u] + sbh[256 + u], Cz1 = sC[257 + u] + sbh[257 + u];
                    const float Cn0 = sC[512 + u], Cn1 = sC[513 + u];
                    const float bn0 = sbh[512 + u], bn1 = sbh[513 + u];
                    const float wo0 = swo[u], wo1 = swo[u + 1];
                    #pragma unroll
                    for (int rh = 0; rh < 2; rh++) {
                        const int R = wr + g + 8 * rh;
                        const float x = (rh == 0) ? x0 : x1;

                        float gr0 = fmaf(x, Ar0, Cr0) + acc[jm][2 * rh];
                        float gz0 = fmaf(x, Az0, Cz0) + acc[4 + jm][2 * rh];
                        float r0  = fast_sig(gr0);
                        float z0  = fast_sig(gz0);
                        float n0  = fast_tanh(fmaf(r0, acc[8 + jm][2 * rh] + bn0, fmaf(x, An0, Cn0)));
                        float ho0 = sh[R * PITCH + u];
                        float hn0 = fmaf(z0, ho0 - n0, n0);

                        float gr1 = fmaf(x, Ar1, Cr1) + acc[jm][2 * rh + 1];
                        float gz1 = fmaf(x, Az1, Cz1) + acc[4 + jm][2 * rh + 1];
                        float r1  = fast_sig(gr1);
                        float z1  = fast_sig(gz1);
                        float n1  = fast_tanh(fmaf(r1, acc[8 + jm][2 * rh + 1] + bn1, fmaf(x, An1, Cn1)));
                        float ho1 = sh[R * PITCH + u + 1];
                        float hn1 = fmaf(z1, ho1 - n1, n1);

                        float2 st; st.x = hn0; st.y = hn1;
                        *(float2*)(g_h + (size_t)(row0 + R) * HD + u) = st;

                        float p = fmaf(hn0, wo0, hn1 * wo1);
                        if (rh == 0) pr0 += p; else pr1 += p;
                    }
                }
            }

            __syncthreads();   // protect buf[cur] before next iter's prefetch
        }

        // pred reduce over quad lanes; result valid on all 4 -> x in regs
        pr0 += __shfl_xor_sync(0xffffffffu, pr0, 1);
        pr0 += __shfl_xor_sync(0xffffffffu, pr0, 2);
        pr1 += __shfl_xor_sync(0xffffffffu, pr1, 1);
        pr1 += __shfl_xor_sync(0xffffffffu, pr1, 2);

        x0 = pr0 + bo;
        x1 = pr1 + bo;

        if (tg == 0) {
            const int R0 = wr + g, R1 = R0 + 8;
            out[(size_t)(row0 + R0) * TSTEPS + t] = x0;
            out[(size_t)(row0 + R1) * TSTEPS + t] = x1;
        }
    }
}

// ---------------------------------------------------------------------------
extern "C" void kernel_launch(void* const* d_in, const int* in_sizes, int n_in,
                              void* d_out, int out_size)
{
    const float* enc    = (const float*)d_in[0];
    const float* w_proj = (const float*)d_in[1];
    const float* b_proj = (const float*)d_in[2];
    const float* W_ih   = (const float*)d_in[3];
    const float* b_ih   = (const float*)d_in[4];
    const float* W_hh   = (const float*)d_in[5];
    const float* b_hh   = (const float*)d_in[6];
    const float* w_out  = (const float*)d_in[7];
    const float* b_out  = (const float*)d_in[8];
    float* out = (float*)d_out;

    cudaFuncSetAttribute(decode_kernel,
                         cudaFuncAttributeMaxDynamicSharedMemorySize, SMEM_BYTES);

    init_kernel<<<256, 256>>>(enc, w_proj, b_proj, W_ih, b_ih, W_hh);
    decode_kernel<<<NBLK, 256, SMEM_BYTES>>>(b_hh, w_out, b_out, out);
}